// round 6
// baseline (speedup 1.0000x reference)
#include <cuda_runtime.h>
#include <cuda_bf16.h>
#include <cstdint>

// ---------------- problem constants ----------------
#define N_TOK 8192
#define H_DIM 4096
#define V_DIM 32000
#define MT 128                  // token rows per CTA
#define NT 128                  // vocab cols per CTA
#define KCH 32                  // bf16 K elements per chunk (64 bytes)
#define NKC (H_DIM / KCH)       // 128 chunks
#define PITCH 80                // smem row pitch (64 data + 16 pad, conflict-free ldmatrix)
#define A_OFF 0
#define B_OFF (MT * PITCH)      // 10240
#define STB (B_OFF + NT * PITCH)  // 20480 per stage
#define NSTG 4
#define PART_OFF (NSTG * STB)     // 81920
#define SMEM_TOTAL (PART_OFF + 4096)  // 86016 per CTA (x2 CTAs = 172KB < 228KB)
#define NSPLIT (V_DIM / NT)     // 250
#define SPLIT_STRIDE 256
#define IGNORE_INDEX (-100)

// ---------------- device scratch (no cudaMalloc allowed) ----------------
__device__ __align__(256) __nv_bfloat16 g_A[(size_t)N_TOK * H_DIM];    // 64 MB
__device__ __align__(256) __nv_bfloat16 g_W[(size_t)V_DIM * H_DIM];    // 256 MB
__device__ float g_pm[(size_t)N_TOK * SPLIT_STRIDE];                   // 8 MB
__device__ float g_ps[(size_t)N_TOK * SPLIT_STRIDE];                   // 8 MB
__device__ float g_tl[N_TOK];
__device__ float g_nll[N_TOK];
__device__ int   g_tgt[N_TOK];

// ---------------- helpers ----------------
__device__ __forceinline__ uint32_t smem_u32(const void* p) {
    uint32_t a;
    asm("{ .reg .u64 t; cvta.to.shared.u64 t, %1; cvt.u32.u64 %0, t; }" : "=r"(a) : "l"(p));
    return a;
}
__device__ __forceinline__ void cp16(uint32_t dst, const void* src) {
    asm volatile("cp.async.cg.shared.global [%0], [%1], 16;" :: "r"(dst), "l"(src) : "memory");
}
__device__ __forceinline__ void ldmx4(uint32_t* r, uint32_t addr) {
    asm volatile("ldmatrix.sync.aligned.m8n8.x4.shared.b16 {%0,%1,%2,%3}, [%4];"
                 : "=r"(r[0]), "=r"(r[1]), "=r"(r[2]), "=r"(r[3]) : "r"(addr));
}
__device__ __forceinline__ void mma16816(float* c, const uint32_t* a, uint32_t b0, uint32_t b1) {
    asm volatile("mma.sync.aligned.m16n8k16.row.col.f32.bf16.bf16.f32 "
                 "{%0,%1,%2,%3}, {%4,%5,%6,%7}, {%8,%9}, {%0,%1,%2,%3};"
                 : "+f"(c[0]), "+f"(c[1]), "+f"(c[2]), "+f"(c[3])
                 : "r"(a[0]), "r"(a[1]), "r"(a[2]), "r"(a[3]), "r"(b0), "r"(b1));
}

// FFMA-only exp (avoids MUFU EX2 throughput wall in the epilogue)
__device__ __forceinline__ float fastexp(float x) {
    x = fmaxf(x, -80.0f);
    float t = fmaf(x, 1.4426950408889634f, 12582912.0f);
    int ib = __float_as_int(t) << 23;
    float n = t - 12582912.0f;
    float r = fmaf(n, -0.6931471805599453f, x);
    float q = 8.3333333e-3f;
    q = fmaf(q, r, 4.1666667e-2f);
    q = fmaf(q, r, 1.6666667e-1f);
    q = fmaf(q, r, 0.5f);
    q = fmaf(q, r, 1.0f);
    q = fmaf(q, r, 1.0f);
    return __int_as_float(__float_as_int(q) + ib);
}

// ---------------- target normalization (int32 vs int64 layout probe) ----------------
__global__ void prep_targets(const int* __restrict__ w) {
    __shared__ int is64;
    if (threadIdx.x == 0) {
        int f = 1;
        for (int i = 0; i < 64; i++) {
            int hi = w[2 * i + 1];
            if (hi != 0 && hi != -1) { f = 0; break; }
        }
        is64 = f;
    }
    __syncthreads();
    int mode = is64;
    for (int i = threadIdx.x; i < N_TOK; i += blockDim.x)
        g_tgt[i] = mode ? w[2 * i] : w[i];
}

// ---------------- fp32 -> bf16 conversion ----------------
__device__ __forceinline__ void conv_body(const float* __restrict__ src, __nv_bfloat16* dst, int n4) {
    int i = blockIdx.x * blockDim.x + threadIdx.x;
    if (i < n4) {
        float4 v = ((const float4*)src)[i];
        __nv_bfloat162* d2 = (__nv_bfloat162*)dst;
        d2[2 * i]     = __floats2bfloat162_rn(v.x, v.y);
        d2[2 * i + 1] = __floats2bfloat162_rn(v.z, v.w);
    }
}
__global__ void conv_A_kernel(const float* __restrict__ src) { conv_body(src, g_A, N_TOK * H_DIM / 4); }
__global__ void conv_W_kernel(const float* __restrict__ src) { conv_body(src, g_W, (int)((size_t)V_DIM * H_DIM / 4)); }

// ---------------- fused GEMM + partial softmax ----------------
// 2 CTAs/SM: one CTA's wait/barrier stalls are covered by the other's MMAs.
// grid (64 mt, 250 ct), x fastest: bf16 A (64 MB) stays L2-resident, W streams.
__global__ void __launch_bounds__(256, 2) ce_gemm(void) {
    extern __shared__ char smem[];
    uint32_t sb = smem_u32(smem);
    uint32_t part = sb + PART_OFF;
    int tid = threadIdx.x;
    int wid = tid >> 5, lane = tid & 31;
    int mwid = wid >> 2, nwid = wid & 3;    // warp grid 2 (M) x 4 (N)
    int mt = blockIdx.x, ct = blockIdx.y;

    // hoisted cp.async addressing: this thread's fixed row/16B-slot, pointer += 64B/chunk
    int r = tid >> 2, cc = tid & 3;         // rows 0..63 via i-loop offset
    const char* srcA0 = (const char*)(g_A + (size_t)(mt * MT + r) * H_DIM) + cc * 16;
    const char* srcA1 = srcA0 + (size_t)64 * H_DIM * 2;
    const char* srcB0 = (const char*)(g_W + (size_t)(ct * NT + r) * H_DIM) + cc * 16;
    const char* srcB1 = srcB0 + (size_t)64 * H_DIM * 2;
    uint32_t dA0 = sb + A_OFF + (uint32_t)(r * PITCH + cc * 16);
    uint32_t dA1 = dA0 + 64 * PITCH;
    uint32_t dB0 = sb + B_OFF + (uint32_t)(r * PITCH + cc * 16);
    uint32_t dB1 = dB0 + 64 * PITCH;

    auto load_chunk = [&](int c) {
        uint32_t so = (uint32_t)((c & (NSTG - 1)) * STB);
        size_t go = (size_t)c * 64;
        cp16(dA0 + so, srcA0 + go);
        cp16(dA1 + so, srcA1 + go);
        cp16(dB0 + so, srcB0 + go);
        cp16(dB1 + so, srcB1 + go);
        asm volatile("cp.async.commit_group;" ::: "memory");
    };

    float acc[4][4][4];   // [mi 16-row group][ni 8-col group][frag]
    #pragma unroll
    for (int a = 0; a < 4; a++)
        #pragma unroll
        for (int b = 0; b < 4; b++)
            #pragma unroll
            for (int c = 0; c < 4; c++) acc[a][b][c] = 0.0f;

    load_chunk(0);
    load_chunk(1);
    load_chunk(2);

    int lrow = (lane & 7) + ((lane >> 3) & 1) * 8;   // row within 16-row tile
    int lkhalf = ((lane >> 4) & 1) * 16;             // 16B half of the 32B k16-step
    uint32_t a_base0 = sb + A_OFF + (uint32_t)((mwid * 64 + lrow) * PITCH + lkhalf);
    uint32_t b_base0 = sb + B_OFF + (uint32_t)((nwid * 32 + lrow) * PITCH + lkhalf);

    for (int kb = 0; kb < NKC; kb++) {
        if (kb < NKC - 2)      { asm volatile("cp.async.wait_group 2;" ::: "memory"); }
        else if (kb == NKC - 2){ asm volatile("cp.async.wait_group 1;" ::: "memory"); }
        else                   { asm volatile("cp.async.wait_group 0;" ::: "memory"); }
        __syncthreads();
        if (kb + 3 < NKC) load_chunk(kb + 3);

        uint32_t so = (uint32_t)((kb & (NSTG - 1)) * STB);
        uint32_t a_base = a_base0 + so;
        uint32_t b_base = b_base0 + so;

        #pragma unroll
        for (int ks = 0; ks < 2; ks++) {       // 2 x k16 steps cover the 32-chunk
            uint32_t koff = (uint32_t)(ks * 32);
            uint32_t af[4][4];
            #pragma unroll
            for (int mi = 0; mi < 4; mi++)
                ldmx4(af[mi], a_base + (uint32_t)(mi * 16 * PITCH) + koff);
            uint32_t br[2][4];
            #pragma unroll
            for (int g = 0; g < 2; g++)
                ldmx4(br[g], b_base + (uint32_t)(g * 16 * PITCH) + koff);
            #pragma unroll
            for (int mi = 0; mi < 4; mi++) {
                #pragma unroll
                for (int ni = 0; ni < 4; ni++) {
                    int g = ni >> 1, s = ni & 1;
                    mma16816(acc[mi][ni], af[mi], br[g][s], br[g][s + 2]);
                }
            }
        }
    }
    __syncthreads();

    // ---- epilogue: fused partial softmax over this CTA's 128x128 logits ----
    const float NEG_INF = __int_as_float(0xff800000);
    #pragma unroll
    for (int mi = 0; mi < 4; mi++) {
        #pragma unroll
        for (int rs = 0; rs < 2; rs++) {
            int row = mwid * 64 + mi * 16 + (lane >> 2) + rs * 8;
            int token = mt * MT + row;
            int tg = g_tgt[token];
            float v[8];
            #pragma unroll
            for (int ni = 0; ni < 4; ni++) {
                v[ni * 2]     = acc[mi][ni][rs * 2];
                v[ni * 2 + 1] = acc[mi][ni][rs * 2 + 1];
            }
            #pragma unroll
            for (int ni = 0; ni < 4; ni++)
                #pragma unroll
                for (int j = 0; j < 2; j++) {
                    int gcol = ct * NT + nwid * 32 + ni * 8 + (lane & 3) * 2 + j;
                    if (gcol == tg) g_tl[token] = v[ni * 2 + j];
                }
            float m = NEG_INF;
            #pragma unroll
            for (int j = 0; j < 8; j++) m = fmaxf(m, v[j]);
            m = fmaxf(m, __shfl_xor_sync(0xffffffffu, m, 1));
            m = fmaxf(m, __shfl_xor_sync(0xffffffffu, m, 2));
            float s = 0.0f;
            #pragma unroll
            for (int j = 0; j < 8; j++) s += fastexp(v[j] - m);
            s += __shfl_xor_sync(0xffffffffu, s, 1);
            s += __shfl_xor_sync(0xffffffffu, s, 2);
            if ((lane & 3) == 0) {
                uint32_t off = part + (uint32_t)((row * 4 + nwid) * 8);
                asm volatile("st.shared.v2.f32 [%0], {%1, %2};" :: "r"(off), "f"(m), "f"(s) : "memory");
            }
        }
    }
    __syncthreads();
    if (tid < MT) {
        int row = tid;
        int token = mt * MT + row;
        float M = NEG_INF, S = 0.0f;
        #pragma unroll
        for (int w = 0; w < 4; w++) {
            float2 p;
            asm volatile("ld.shared.v2.f32 {%0, %1}, [%2];"
                         : "=f"(p.x), "=f"(p.y) : "r"(part + (uint32_t)((row * 4 + w) * 8)));
            float nm = fmaxf(M, p.x);
            S = S * fastexp(M - nm) + p.y * fastexp(p.x - nm);
            M = nm;
        }
        g_pm[(size_t)token * SPLIT_STRIDE + ct] = M;
        g_ps[(size_t)token * SPLIT_STRIDE + ct] = S;
    }
}

// ---------------- per-token logsumexp merge over 250 splits (1 warp / token) ----------------
__global__ void reduce_lse(void) {
    int warp = (blockIdx.x * blockDim.x + threadIdx.x) >> 5;
    int lane = threadIdx.x & 31;
    if (warp >= N_TOK) return;
    int token = warp;
    const float NEG_INF = __int_as_float(0xff800000);
    float lm[8], ls[8];
    #pragma unroll
    for (int i = 0; i < 8; i++) {
        int j = lane + i * 32;
        if (j < NSPLIT) {
            lm[i] = g_pm[(size_t)token * SPLIT_STRIDE + j];
            ls[i] = g_ps[(size_t)token * SPLIT_STRIDE + j];
        } else { lm[i] = NEG_INF; ls[i] = 0.0f; }
    }
    float M = NEG_INF;
    #pragma unroll
    for (int i = 0; i < 8; i++) M = fmaxf(M, lm[i]);
    #pragma unroll
    for (int o = 16; o; o >>= 1) M = fmaxf(M, __shfl_xor_sync(0xffffffffu, M, o));
    float S = 0.0f;
    #pragma unroll
    for (int i = 0; i < 8; i++) S += ls[i] * fastexp(lm[i] - M);
    #pragma unroll
    for (int o = 16; o; o >>= 1) S += __shfl_xor_sync(0xffffffffu, S, o);
    if (lane == 0) {
        int t = g_tgt[token];
        float nll = (t != IGNORE_INDEX) ? (M + logf(S) - g_tl[token]) : 0.0f;
        g_nll[token] = nll;
    }
}

// ---------------- final deterministic tree reduction ----------------
__global__ void reduce_final(float* __restrict__ out) {
    __shared__ float ss[1024];
    __shared__ int sc[1024];
    int tid = threadIdx.x;
    float s = 0.0f; int c = 0;
    for (int i = tid; i < N_TOK; i += 1024) {
        s += g_nll[i];
        c += (g_tgt[i] != IGNORE_INDEX) ? 1 : 0;
    }
    ss[tid] = s; sc[tid] = c;
    __syncthreads();
    for (int o = 512; o; o >>= 1) {
        if (tid < o) { ss[tid] += ss[tid + o]; sc[tid] += sc[tid + o]; }
        __syncthreads();
    }
    if (tid == 0) {
        int nv = sc[0] > 0 ? sc[0] : 1;
        out[0] = ss[0] / (float)nv;
    }
}

// ---------------- launch ----------------
extern "C" void kernel_launch(void* const* d_in, const int* in_sizes, int n_in,
                              void* d_out, int out_size) {
    (void)in_sizes; (void)n_in; (void)out_size;
    const float* input  = (const float*)d_in[0];
    const float* weight = (const float*)d_in[1];
    const int*   traw   = (const int*)d_in[2];
    float* out = (float*)d_out;

    prep_targets<<<1, 256>>>(traw);

    int nA4 = N_TOK * H_DIM / 4;
    int nW4 = (int)((size_t)V_DIM * H_DIM / 4);
    conv_A_kernel<<<(nA4 + 255) / 256, 256>>>(input);
    conv_W_kernel<<<(nW4 + 255) / 256, 256>>>(weight);

    cudaFuncSetAttribute(ce_gemm, cudaFuncAttributeMaxDynamicSharedMemorySize, SMEM_TOTAL);
    dim3 grid(N_TOK / MT, V_DIM / NT);   // (64, 250)
    ce_gemm<<<grid, 256, SMEM_TOTAL>>>();

    reduce_lse<<<(N_TOK * 32) / 256, 256>>>();
    reduce_final<<<1, 1024>>>(out);
}

// round 7
// speedup vs baseline: 1.0873x; 1.0873x over previous
#include <cuda_runtime.h>
#include <cuda_bf16.h>
#include <cstdint>

// ---------------- problem constants ----------------
#define N_TOK 8192
#define H_DIM 4096
#define V_DIM 32000
#define MT 128                  // token rows per CTA
#define NT 256                  // vocab cols per CTA
#define KCH 64                  // bf16 K elements per chunk (128 bytes)
#define NKC (H_DIM / KCH)       // 64 chunks
#define PITCH 144               // smem row pitch (128 data + 16 pad, conflict-free ldmatrix)
#define A_ST (MT * PITCH)       // 18432
#define B_ST (NT * PITCH)       // 36864
#define STB (A_ST + B_ST)       // 55296 per stage
#define NSTG 3
#define TILES_OFF 4096
#define SMEM_TOTAL (TILES_OFF + NSTG * STB)   // 169984
#define NSPLIT (V_DIM / NT)     // 125
#define SPLIT_STRIDE 128
#define IGNORE_INDEX (-100)

// ---------------- device scratch (no cudaMalloc allowed) ----------------
__device__ __align__(256) __nv_bfloat16 g_A[(size_t)N_TOK * H_DIM];    // 64 MB
__device__ __align__(256) __nv_bfloat16 g_W[(size_t)V_DIM * H_DIM];    // 256 MB
__device__ float g_pm[(size_t)N_TOK * SPLIT_STRIDE];                   // 4 MB
__device__ float g_ps[(size_t)N_TOK * SPLIT_STRIDE];                   // 4 MB
__device__ float g_tl[N_TOK];
__device__ float g_nll[N_TOK];
__device__ int   g_tgt[N_TOK];

// ---------------- helpers ----------------
__device__ __forceinline__ uint32_t smem_u32(const void* p) {
    uint32_t a;
    asm("{ .reg .u64 t; cvta.to.shared.u64 t, %1; cvt.u32.u64 %0, t; }" : "=r"(a) : "l"(p));
    return a;
}
__device__ __forceinline__ void cp16(uint32_t dst, const void* src) {
    asm volatile("cp.async.cg.shared.global [%0], [%1], 16;" :: "r"(dst), "l"(src) : "memory");
}
__device__ __forceinline__ void ldmx4(uint32_t* r, uint32_t addr) {
    asm volatile("ldmatrix.sync.aligned.m8n8.x4.shared.b16 {%0,%1,%2,%3}, [%4];"
                 : "=r"(r[0]), "=r"(r[1]), "=r"(r[2]), "=r"(r[3]) : "r"(addr));
}
__device__ __forceinline__ void mma16816(float* c, const uint32_t* a, uint32_t b0, uint32_t b1) {
    asm volatile("mma.sync.aligned.m16n8k16.row.col.f32.bf16.bf16.f32 "
                 "{%0,%1,%2,%3}, {%4,%5,%6,%7}, {%8,%9}, {%0,%1,%2,%3};"
                 : "+f"(c[0]), "+f"(c[1]), "+f"(c[2]), "+f"(c[3])
                 : "r"(a[0]), "r"(a[1]), "r"(a[2]), "r"(a[3]), "r"(b0), "r"(b1));
}

// FFMA-only exp (avoids MUFU EX2 throughput wall in the epilogue)
__device__ __forceinline__ float fastexp(float x) {
    x = fmaxf(x, -80.0f);
    float t = fmaf(x, 1.4426950408889634f, 12582912.0f);
    int ib = __float_as_int(t) << 23;
    float n = t - 12582912.0f;
    float r = fmaf(n, -0.6931471805599453f, x);
    float q = 8.3333333e-3f;
    q = fmaf(q, r, 4.1666667e-2f);
    q = fmaf(q, r, 1.6666667e-1f);
    q = fmaf(q, r, 0.5f);
    q = fmaf(q, r, 1.0f);
    q = fmaf(q, r, 1.0f);
    return __int_as_float(__float_as_int(q) + ib);
}

// ---------------- target normalization (int32 vs int64 layout probe) ----------------
__global__ void prep_targets(const int* __restrict__ w) {
    __shared__ int is64;
    if (threadIdx.x == 0) {
        int f = 1;
        for (int i = 0; i < 64; i++) {
            int hi = w[2 * i + 1];
            if (hi != 0 && hi != -1) { f = 0; break; }
        }
        is64 = f;
    }
    __syncthreads();
    int mode = is64;
    for (int i = threadIdx.x; i < N_TOK; i += blockDim.x)
        g_tgt[i] = mode ? w[2 * i] : w[i];
}

// ---------------- fp32 -> bf16 conversion ----------------
__device__ __forceinline__ void conv_body(const float* __restrict__ src, __nv_bfloat16* dst, int n4) {
    int i = blockIdx.x * blockDim.x + threadIdx.x;
    if (i < n4) {
        float4 v = ((const float4*)src)[i];
        __nv_bfloat162* d2 = (__nv_bfloat162*)dst;
        d2[2 * i]     = __floats2bfloat162_rn(v.x, v.y);
        d2[2 * i + 1] = __floats2bfloat162_rn(v.z, v.w);
    }
}
__global__ void conv_A_kernel(const float* __restrict__ src) { conv_body(src, g_A, N_TOK * H_DIM / 4); }
__global__ void conv_W_kernel(const float* __restrict__ src) { conv_body(src, g_W, (int)((size_t)V_DIM * H_DIM / 4)); }

// ---------------- fused GEMM + partial softmax ----------------
// 8 fat warps (64x64 warptile): big register budget (256/thread) lets the
// compiler pipeline LDSM fragments across MMA bursts; halves smem fragment
// traffic per MAC vs 64x32 warptiles. grid (64, 125), x fastest: A L2-resident.
__global__ void __launch_bounds__(256, 1) ce_gemm(void) {
    extern __shared__ char smem[];
    uint32_t sb = smem_u32(smem);
    uint32_t part = sb;                    // 4 KB: [row][nwid] float2 partials
    uint32_t tiles = sb + TILES_OFF;
    int tid = threadIdx.x;
    int wid = tid >> 5, lane = tid & 31;
    int mwid = wid >> 2, nwid = wid & 3;   // warp grid 2 (M) x 4 (N)
    int mt = blockIdx.x, ct = blockIdx.y;

    // hoisted cp.async bases: thread's fixed (row, 16B-slot); iters use imm offsets
    int r = tid >> 3, cc = tid & 7;        // 32 rows per iter
    const char* srcA = (const char*)(g_A + (size_t)(mt * MT + r) * H_DIM) + cc * 16;
    const char* srcB = (const char*)(g_W + (size_t)(ct * NT + r) * H_DIM) + cc * 16;
    uint32_t dA = tiles + (uint32_t)(r * PITCH + cc * 16);
    uint32_t dB = tiles + A_ST + (uint32_t)(r * PITCH + cc * 16);

    auto load_chunk = [&](int c, int s) {
        uint32_t so = (uint32_t)(s * STB);
        size_t go = (size_t)c * 128;       // 128 bytes per chunk along K
        #pragma unroll
        for (int i = 0; i < 4; i++)        // A: 128 rows
            cp16(dA + so + (uint32_t)(i * 32 * PITCH),
                 srcA + go + (size_t)i * 32 * H_DIM * 2);
        #pragma unroll
        for (int i = 0; i < 8; i++)        // B: 256 rows
            cp16(dB + so + (uint32_t)(i * 32 * PITCH),
                 srcB + go + (size_t)i * 32 * H_DIM * 2);
        asm volatile("cp.async.commit_group;" ::: "memory");
    };

    float acc[4][8][4];   // [mi 16-row][ni 8-col group][frag] = 128 regs
    #pragma unroll
    for (int a = 0; a < 4; a++)
        #pragma unroll
        for (int b = 0; b < 8; b++)
            #pragma unroll
            for (int c = 0; c < 4; c++) acc[a][b][c] = 0.0f;

    load_chunk(0, 0);
    load_chunk(1, 1);

    int lrow = (lane & 7) + ((lane >> 3) & 1) * 8;   // row within 16-row tile
    int lkhalf = ((lane >> 4) & 1) * 16;             // 16B half of the 32B k16-step
    uint32_t a_base0 = tiles + (uint32_t)((mwid * 64 + lrow) * PITCH + lkhalf);
    uint32_t b_base0 = tiles + A_ST + (uint32_t)((nwid * 64 + lrow) * PITCH + lkhalf);

    int stage = 0;                         // stage of chunk kb
    for (int kb = 0; kb < NKC; kb++) {
        if (kb < NKC - 1) { asm volatile("cp.async.wait_group 1;" ::: "memory"); }
        else              { asm volatile("cp.async.wait_group 0;" ::: "memory"); }
        __syncthreads();
        int ps = stage + 2; if (ps >= NSTG) ps -= NSTG;  // free stage to refill
        if (kb + 2 < NKC) load_chunk(kb + 2, ps);

        uint32_t so = (uint32_t)(stage * STB);
        uint32_t a_base = a_base0 + so;
        uint32_t b_base = b_base0 + so;

        #pragma unroll
        for (int ks = 0; ks < 4; ks++) {   // 4 x k16 steps cover the 64-chunk
            uint32_t koff = (uint32_t)(ks * 32);
            uint32_t af[4][4];
            #pragma unroll
            for (int mi = 0; mi < 4; mi++)
                ldmx4(af[mi], a_base + (uint32_t)(mi * 16 * PITCH) + koff);
            uint32_t br[4][4];
            #pragma unroll
            for (int g = 0; g < 4; g++)
                ldmx4(br[g], b_base + (uint32_t)(g * 16 * PITCH) + koff);
            #pragma unroll
            for (int mi = 0; mi < 4; mi++) {
                #pragma unroll
                for (int ni = 0; ni < 8; ni++) {
                    int g = ni >> 1, s = ni & 1;
                    mma16816(acc[mi][ni], af[mi], br[g][s], br[g][s + 2]);
                }
            }
        }
        if (++stage >= NSTG) stage = 0;
    }
    __syncthreads();

    // ---- epilogue: fused partial softmax over this CTA's 128x256 logits ----
    const float NEG_INF = __int_as_float(0xff800000);
    #pragma unroll
    for (int mi = 0; mi < 4; mi++) {
        #pragma unroll
        for (int rs = 0; rs < 2; rs++) {
            int row = mwid * 64 + mi * 16 + (lane >> 2) + rs * 8;
            int token = mt * MT + row;
            int tg = g_tgt[token];
            float v[16];
            #pragma unroll
            for (int ni = 0; ni < 8; ni++) {
                v[ni * 2]     = acc[mi][ni][rs * 2];
                v[ni * 2 + 1] = acc[mi][ni][rs * 2 + 1];
            }
            // target logit capture
            #pragma unroll
            for (int ni = 0; ni < 8; ni++)
                #pragma unroll
                for (int j = 0; j < 2; j++) {
                    int gcol = ct * NT + nwid * 64 + ni * 8 + (lane & 3) * 2 + j;
                    if (gcol == tg) g_tl[token] = v[ni * 2 + j];
                }
            float m = NEG_INF;
            #pragma unroll
            for (int j = 0; j < 16; j++) m = fmaxf(m, v[j]);
            m = fmaxf(m, __shfl_xor_sync(0xffffffffu, m, 1));
            m = fmaxf(m, __shfl_xor_sync(0xffffffffu, m, 2));
            float s = 0.0f;
            #pragma unroll
            for (int j = 0; j < 16; j++) s += fastexp(v[j] - m);
            s += __shfl_xor_sync(0xffffffffu, s, 1);
            s += __shfl_xor_sync(0xffffffffu, s, 2);
            if ((lane & 3) == 0) {
                uint32_t off = part + (uint32_t)((row * 4 + nwid) * 8);
                asm volatile("st.shared.v2.f32 [%0], {%1, %2};" :: "r"(off), "f"(m), "f"(s) : "memory");
            }
        }
    }
    __syncthreads();
    if (tid < MT) {
        int row = tid;
        int token = mt * MT + row;
        float M = NEG_INF, S = 0.0f;
        #pragma unroll
        for (int w = 0; w < 4; w++) {
            float2 p;
            asm volatile("ld.shared.v2.f32 {%0, %1}, [%2];"
                         : "=f"(p.x), "=f"(p.y) : "r"(part + (uint32_t)((row * 4 + w) * 8)));
            float nm = fmaxf(M, p.x);
            S = S * fastexp(M - nm) + p.y * fastexp(p.x - nm);
            M = nm;
        }
        g_pm[(size_t)token * SPLIT_STRIDE + ct] = M;
        g_ps[(size_t)token * SPLIT_STRIDE + ct] = S;
    }
}

// ---------------- per-token logsumexp merge over 125 splits (1 warp / token) ----------------
__global__ void reduce_lse(void) {
    int warp = (blockIdx.x * blockDim.x + threadIdx.x) >> 5;
    int lane = threadIdx.x & 31;
    if (warp >= N_TOK) return;
    int token = warp;
    const float NEG_INF = __int_as_float(0xff800000);
    float lm[4], ls[4];
    #pragma unroll
    for (int i = 0; i < 4; i++) {
        int j = lane + i * 32;
        if (j < NSPLIT) {
            lm[i] = g_pm[(size_t)token * SPLIT_STRIDE + j];
            ls[i] = g_ps[(size_t)token * SPLIT_STRIDE + j];
        } else { lm[i] = NEG_INF; ls[i] = 0.0f; }
    }
    float M = NEG_INF;
    #pragma unroll
    for (int i = 0; i < 4; i++) M = fmaxf(M, lm[i]);
    #pragma unroll
    for (int o = 16; o; o >>= 1) M = fmaxf(M, __shfl_xor_sync(0xffffffffu, M, o));
    float S = 0.0f;
    #pragma unroll
    for (int i = 0; i < 4; i++) S += ls[i] * fastexp(lm[i] - M);
    #pragma unroll
    for (int o = 16; o; o >>= 1) S += __shfl_xor_sync(0xffffffffu, S, o);
    if (lane == 0) {
        int t = g_tgt[token];
        float nll = (t != IGNORE_INDEX) ? (M + logf(S) - g_tl[token]) : 0.0f;
        g_nll[token] = nll;
    }
}

// ---------------- final deterministic tree reduction ----------------
__global__ void reduce_final(float* __restrict__ out) {
    __shared__ float ss[1024];
    __shared__ int sc[1024];
    int tid = threadIdx.x;
    float s = 0.0f; int c = 0;
    for (int i = tid; i < N_TOK; i += 1024) {
        s += g_nll[i];
        c += (g_tgt[i] != IGNORE_INDEX) ? 1 : 0;
    }
    ss[tid] = s; sc[tid] = c;
    __syncthreads();
    for (int o = 512; o; o >>= 1) {
        if (tid < o) { ss[tid] += ss[tid + o]; sc[tid] += sc[tid + o]; }
        __syncthreads();
    }
    if (tid == 0) {
        int nv = sc[0] > 0 ? sc[0] : 1;
        out[0] = ss[0] / (float)nv;
    }
}

// ---------------- launch ----------------
extern "C" void kernel_launch(void* const* d_in, const int* in_sizes, int n_in,
                              void* d_out, int out_size) {
    (void)in_sizes; (void)n_in; (void)out_size;
    const float* input  = (const float*)d_in[0];
    const float* weight = (const float*)d_in[1];
    const int*   traw   = (const int*)d_in[2];
    float* out = (float*)d_out;

    prep_targets<<<1, 256>>>(traw);

    int nA4 = N_TOK * H_DIM / 4;
    int nW4 = (int)((size_t)V_DIM * H_DIM / 4);
    conv_A_kernel<<<(nA4 + 255) / 256, 256>>>(input);
    conv_W_kernel<<<(nW4 + 255) / 256, 256>>>(weight);

    cudaFuncSetAttribute(ce_gemm, cudaFuncAttributeMaxDynamicSharedMemorySize, SMEM_TOTAL);
    dim3 grid(N_TOK / MT, V_DIM / NT);   // (64, 125)
    ce_gemm<<<grid, 256, SMEM_TOTAL>>>();

    reduce_lse<<<(N_TOK * 32) / 256, 256>>>();
    reduce_final<<<1, 1024>>>(out);
}